// round 3
// baseline (speedup 1.0000x reference)
#include <cuda_runtime.h>

#define NN     100000
#define NFEAT  512
#define HID    16
#define NCLASS 40
#define EMAX   3200000

// ---------------- scratch (static device globals; no allocation) ----------------
__device__ float g_deg[NN];
__device__ float g_dinv[NN];
__device__ float g_ew[EMAX];
__device__ float g_W1[NFEAT * 64];          // packed [f][c]: c<32 -> iw1[k=c/16][f][c%16], c>=32 -> rw1
__device__ float g_HR[(size_t)NN * 64];     // [n][c]: c<32 = x@iw1 (k-major), c>=32 = x@rw1
__device__ float g_agg1[(size_t)NN * 32];   // scatter target layer 1
__device__ float g_h1[NN * HID];            // layer-1 output
__device__ float g_agg2[NN * HID];          // scatter target layer 2 (pre-transform!)
__device__ float g_W2[HID * 160];           // packed [f][c]: c<80 -> iw2[k=c/40][f][c%40], c>=80 -> rw2

// ---------------- helpers ----------------
__device__ __forceinline__ void red_add_v4(float* p, float a, float b, float c, float d) {
    asm volatile("red.global.add.v4.f32 [%0], {%1,%2,%3,%4};"
                 :: "l"(p), "f"(a), "f"(b), "f"(c), "f"(d) : "memory");
}

// ---------------- kernels ----------------
__global__ void zero_kernel() {
    int i = blockIdx.x * blockDim.x + threadIdx.x;
    if (i < NN) g_deg[i] = 0.f;
    if (i < NN * 32) g_agg1[i] = 0.f;
    if (i < NN * 16) g_agg2[i] = 0.f;
}

__global__ void pack_w1(const float* __restrict__ iw1, const float* __restrict__ rw1) {
    int i = blockIdx.x * blockDim.x + threadIdx.x;
    if (i >= NFEAT * 64) return;
    int f = i >> 6, c = i & 63;
    float v;
    if (c < 32) { int k = c >> 4, j = c & 15; v = iw1[(k * NFEAT + f) * HID + j]; }
    else        { int c2 = c - 32; int k = c2 >> 4, j = c2 & 15; v = rw1[(k * NFEAT + f) * HID + j]; }
    g_W1[i] = v;
}

__global__ void pack_w2(const float* __restrict__ iw2, const float* __restrict__ rw2) {
    int i = blockIdx.x * blockDim.x + threadIdx.x;
    if (i >= HID * 160) return;
    int f = i / 160, c = i % 160;
    float v;
    if (c < 80) { int k = c / 40, o = c % 40; v = iw2[(k * HID + f) * NCLASS + o]; }
    else        { int c2 = c - 80; int k = c2 / 40, o = c2 % 40; v = rw2[(k * HID + f) * NCLASS + o]; }
    g_W2[i] = v;
}

__global__ void deg_kernel(const int* __restrict__ dst, int E) {
    int e = blockIdx.x * blockDim.x + threadIdx.x;
    if (e < E) atomicAdd(&g_deg[__ldg(dst + e)], 1.0f);
}

__global__ void dinv_kernel() {
    int n = blockIdx.x * blockDim.x + threadIdx.x;
    if (n < NN) { float d = g_deg[n]; g_dinv[n] = (d > 0.f) ? rsqrtf(d) : 0.f; }
}

__global__ void ew_kernel(const int* __restrict__ src, const int* __restrict__ dst, int E) {
    int e = blockIdx.x * blockDim.x + threadIdx.x;
    if (e < E) g_ew[e] = g_dinv[__ldg(src + e)] * g_dinv[__ldg(dst + e)];
}

// Tiled SGEMM: HR[100000,64] = x[100000,512] @ W1[512,64]
__global__ void gemm1_kernel(const float* __restrict__ x, int nrows) {
    __shared__ float As[32][68];   // [k][node], padded
    __shared__ float Bs[32][64];   // [k][out]
    int tid = threadIdx.x;               // 256 threads
    int tx = tid & 15, ty = tid >> 4;
    int brow = blockIdx.x * 64;
    float acc[4][4];
#pragma unroll
    for (int i = 0; i < 4; i++)
#pragma unroll
        for (int j = 0; j < 4; j++) acc[i][j] = 0.f;

    for (int k0 = 0; k0 < NFEAT; k0 += 32) {
#pragma unroll
        for (int it = 0; it < 2; ++it) {
            int lin = tid + it * 256;       // float4 units, 0..511
            int row = lin >> 3;             // 0..63
            int c4  = lin & 7;              // 0..7
            int gr  = brow + row;
            float4 v = make_float4(0.f, 0.f, 0.f, 0.f);
            if (gr < nrows) v = *(const float4*)&x[(size_t)gr * NFEAT + k0 + c4 * 4];
            As[c4 * 4 + 0][row] = v.x;
            As[c4 * 4 + 1][row] = v.y;
            As[c4 * 4 + 2][row] = v.z;
            As[c4 * 4 + 3][row] = v.w;
        }
#pragma unroll
        for (int it = 0; it < 2; ++it) {
            int lin = tid + it * 256;
            int row = lin >> 4;             // 0..31
            int c4  = lin & 15;             // 0..15
            *(float4*)&Bs[row][c4 * 4] = *(const float4*)&g_W1[(k0 + row) * 64 + c4 * 4];
        }
        __syncthreads();
#pragma unroll
        for (int kk = 0; kk < 32; ++kk) {
            float4 a4 = *(const float4*)&As[kk][ty * 4];
            float4 b4 = *(const float4*)&Bs[kk][tx * 4];
            float av[4] = {a4.x, a4.y, a4.z, a4.w};
            float bv[4] = {b4.x, b4.y, b4.z, b4.w};
#pragma unroll
            for (int i = 0; i < 4; i++)
#pragma unroll
                for (int j = 0; j < 4; j++) acc[i][j] += av[i] * bv[j];
        }
        __syncthreads();
    }
#pragma unroll
    for (int i = 0; i < 4; i++) {
        int gr = brow + ty * 4 + i;
        if (gr < nrows) {
            float4 o = make_float4(acc[i][0], acc[i][1], acc[i][2], acc[i][3]);
            *(float4*)&g_HR[(size_t)gr * 64 + tx * 4] = o;
        }
    }
}

// Layer-1 scatter: agg1[dst] += ew * HR[src, 0:32]. 8 threads/edge, 16B each.
__global__ void edge1_kernel(const int* __restrict__ src, const int* __restrict__ dst, int E) {
    int idx = blockIdx.x * blockDim.x + threadIdx.x;
    if (idx >= E * 8) return;
    int e = idx >> 3, g = idx & 7;
    int s = __ldg(src + e), d = __ldg(dst + e);
    float w = g_ew[e];
    float4 v = *(const float4*)&g_HR[(size_t)s * 64 + g * 4];
    red_add_v4(&g_agg1[(size_t)d * 32 + g * 4], v.x * w, v.y * w, v.z * w, v.w * w);
}

// Layer-1 epilogue: h1 = mean_k relu(agg1 + x@rw1 + b1)
__global__ void epi1_kernel(const float* __restrict__ b1, int nrows) {
    int i = blockIdx.x * blockDim.x + threadIdx.x;
    if (i >= nrows * HID) return;
    int n = i / HID, j = i - (i / HID) * HID;
    float a0 = g_agg1[(size_t)n * 32 + j]      + g_HR[(size_t)n * 64 + 32 + j] + b1[j];
    float a1 = g_agg1[(size_t)n * 32 + 16 + j] + g_HR[(size_t)n * 64 + 48 + j] + b1[16 + j];
    g_h1[i] = 0.5f * (fmaxf(a0, 0.f) + fmaxf(a1, 0.f));
}

// Layer-2 scatter (PRE-transform): agg2[dst] += ew * h1[src]. 4 threads/edge.
__global__ void edge2_kernel(const int* __restrict__ src, const int* __restrict__ dst, int E) {
    int idx = blockIdx.x * blockDim.x + threadIdx.x;
    if (idx >= E * 4) return;
    int e = idx >> 2, g = idx & 3;
    int s = __ldg(src + e), d = __ldg(dst + e);
    float w = g_ew[e];
    float4 v = *(const float4*)&g_h1[s * HID + g * 4];
    red_add_v4(&g_agg2[d * HID + g * 4], v.x * w, v.y * w, v.z * w, v.w * w);
}

// Layer-2 transform + epilogue: out = mean_k relu(agg2@iw2[k] + h1@rw2[k] + b2[k])
__global__ void out_kernel(const float* __restrict__ b2, float* __restrict__ out, int nrows) {
    __shared__ float Ws[HID * 160];
    int tid = threadIdx.x;   // 320 threads: 8 nodes x 40 outputs
    for (int i = tid; i < HID * 160; i += 320) Ws[i] = g_W2[i];
    __syncthreads();
    int n = blockIdx.x * 8 + tid / 40;
    int o = tid - (tid / 40) * 40;
    if (n >= nrows) return;
    float a[HID], h[HID];
#pragma unroll
    for (int f = 0; f < HID; ++f) {
        a[f] = g_agg2[n * HID + f];
        h[f] = g_h1[n * HID + f];
    }
    float acc0 = b2[o], acc1 = b2[40 + o];
#pragma unroll
    for (int f = 0; f < HID; ++f) {
        const float* wr = &Ws[f * 160];
        acc0 += a[f] * wr[o]      + h[f] * wr[80 + o];
        acc1 += a[f] * wr[40 + o] + h[f] * wr[120 + o];
    }
    out[n * 40 + o] = 0.5f * (fmaxf(acc0, 0.f) + fmaxf(acc1, 0.f));
}

// ---------------- launch ----------------
extern "C" void kernel_launch(void* const* d_in, const int* in_sizes, int n_in,
                              void* d_out, int out_size) {
    const float* x   = (const float*)d_in[0];
    const int*   ei  = (const int*)d_in[1];
    const float* iw1 = (const float*)d_in[2];
    const float* rw1 = (const float*)d_in[3];
    const float* b1  = (const float*)d_in[4];
    const float* iw2 = (const float*)d_in[5];
    const float* rw2 = (const float*)d_in[6];
    const float* b2  = (const float*)d_in[7];
    float* out = (float*)d_out;

    int E = in_sizes[1] / 2;
    const int* src = ei;
    const int* dst = ei + E;

    zero_kernel<<<(NN * 32 + 255) / 256, 256>>>();
    pack_w1<<<(NFEAT * 64 + 255) / 256, 256>>>(iw1, rw1);
    pack_w2<<<(HID * 160 + 255) / 256, 256>>>(iw2, rw2);
    deg_kernel<<<(E + 255) / 256, 256>>>(dst, E);
    dinv_kernel<<<(NN + 255) / 256, 256>>>();
    ew_kernel<<<(E + 255) / 256, 256>>>(src, dst, E);
    gemm1_kernel<<<(NN + 63) / 64, 256>>>(x, NN);
    edge1_kernel<<<(E * 8 + 255) / 256, 256>>>(src, dst, E);
    epi1_kernel<<<(NN * HID + 255) / 256, 256>>>(b1, NN);
    edge2_kernel<<<(E * 4 + 255) / 256, 256>>>(src, dst, E);
    out_kernel<<<(NN + 7) / 8, 320>>>(b2, out, NN);
}